// round 12
// baseline (speedup 1.0000x reference)
#include <cuda_runtime.h>

#define HDIM    128
#define MT      64          // edges per CTA
#define THREADS 256
#define HS_LD   132         // Hi/Hj/X2 row stride (floats)

// Ws: double buffer, 4096 floats (16KB) per half.
// Layer1 chunk: 4 blk x 4 kk x 256 = 4096. Layer2 chunk: 32 x 128 = 4096.
#define WS_HALF 4096
// SMEM floats: Hi 8448 + Hj 8448 + Ws 8192 + W3s 256 + b3s 8 = 25352 (101.4KB) -> 2 CTAs/SM
#define SMEM_FLOATS (8448 + 8448 + 8192 + 256 + 8)
#define SMEM_BYTES  (SMEM_FLOATS * 4)

__device__ __forceinline__ unsigned long long pack2(float x) {
    unsigned long long r;
    asm("mov.b64 %0, {%1, %1};" : "=l"(r) : "f"(x));
    return r;
}
__device__ __forceinline__ unsigned long long pack2f(float lo, float hi) {
    unsigned long long r;
    asm("mov.b64 %0, {%1, %2};" : "=l"(r) : "f"(lo), "f"(hi));
    return r;
}
__device__ __forceinline__ void fma2(unsigned long long& d, unsigned long long a, unsigned long long b) {
    asm("fma.rn.f32x2 %0, %1, %2, %0;" : "+l"(d) : "l"(a), "l"(b));
}
__device__ __forceinline__ float2 unpack2(unsigned long long v) {
    float2 f;
    asm("mov.b64 {%0, %1}, %2;" : "=f"(f.x), "=f"(f.y) : "l"(v));
    return f;
}
__device__ __forceinline__ void cp_async16(float* s, const float* g) {
    unsigned sa = (unsigned)__cvta_generic_to_shared(s);
    asm volatile("cp.async.cg.shared.global [%0], [%1], 16;\n" :: "r"(sa), "l"(g) : "memory");
}
__device__ __forceinline__ void cp_commit() {
    asm volatile("cp.async.commit_group;\n" ::: "memory");
}
template <int N>
__device__ __forceinline__ void cp_wait() {
    asm volatile("cp.async.wait_group %0;\n" :: "n"(N) : "memory");
}

// Issue async copy of weight chunk c into Ws half (c&1). 4096 floats = 1024 f4,
// 4 per thread at 256 threads.
// c in [0,32): W1 chunk (4 blocks x 4 k-rows x 256 cols).
// c in [32,40): W2 chunk (32 k-rows x 128 cols).
__device__ __forceinline__ void issue_chunk(int c, float* Ws,
                                            const float* __restrict__ W1,
                                            const float* __restrict__ W2,
                                            int tid) {
    float* dstb = Ws + (c & 1) * WS_HALF;
    if (c < 32) {
        #pragma unroll
        for (int it = 0; it < 4; it++) {
            int v   = tid + it * THREADS;   // float4 index 0..1023
            int fl  = v * 4;
            int rr  = fl >> 8;              // staged row 0..15
            int col = fl & 255;
            int blk = rr >> 2;
            int kk  = rr & 3;
            const float* g = W1 + (size_t)(blk * HDIM + c * 4 + kk) * 256 + col;
            cp_async16(dstb + rr * 256 + col, g);
        }
    } else {
        int c2 = c - 32;
        #pragma unroll
        for (int it = 0; it < 4; it++) {
            int v   = tid + it * THREADS;
            int fl  = v * 4;
            int rr  = fl >> 7;              // staged row 0..31
            int col = fl & 127;
            const float* g = W2 + (size_t)(c2 * 32 + rr) * 128 + col;
            cp_async16(dstb + rr * 128 + col, g);
        }
    }
    cp_commit();
}

__global__ __launch_bounds__(THREADS, 2)
void entity_linker_kernel(
    const float* __restrict__ node,
    const int*   __restrict__ src,
    const int*   __restrict__ dst,
    const float* __restrict__ W1, const float* __restrict__ b1,
    const float* __restrict__ W2, const float* __restrict__ b2,
    const float* __restrict__ W3, const float* __restrict__ b3,
    float* __restrict__ out, int E)
{
    extern __shared__ float smem[];
    float* Hi  = smem;
    float* Hj  = Hi + MT * HS_LD;
    float* Ws  = Hj + MT * HS_LD;
    float* W3s = Ws + 2 * WS_HALF;     // [2][128] col-major: W3s[c*128+k]
    float* b3s = W3s + 256;

    const int tid = threadIdx.x;
    const int e0  = blockIdx.x * MT;

    // kick off weight chunk 0 ASAP (overlaps the gather)
    issue_chunk(0, Ws, W1, W2, tid);

    // stage W3 (col-major) / b3
    W3s[(tid & 1) * HDIM + (tid >> 1)] = W3[tid];
    if (tid < 2) b3s[tid] = b3[tid];

    // ---- gather Hi / Hj (clamped for tail tile) ----
    #pragma unroll
    for (int it = 0; it < (MT * 32) / THREADS; it++) {
        int v   = tid + it * THREADS;
        int row = v >> 5;
        int seg = v & 31;
        int e = e0 + row; if (e >= E) e = E - 1;
        int s = src[e];
        int d = dst[e];
        float4 a = *(const float4*)(node + (size_t)s * HDIM + seg * 4);
        float4 b = *(const float4*)(node + (size_t)d * HDIM + seg * 4);
        *(float4*)(Hi + row * HS_LD + seg * 4) = a;
        *(float4*)(Hj + row * HS_LD + seg * 4) = b;
    }

    const int tx = tid & 31;          // n-dim: 32 lanes
    const int ty = tid >> 5;          // m-dim: 8 warps, warp owns 8 m-rows
    const int m0 = ty * 8;
    const int n4 = tx * 4;            // lane's base column (4 consecutive floats)

    // Layer-1 accumulators == X1 storage (ReLU applied in place, packed).
    // x1p[i][0..1] = cols n4..n4+3 ; x1p[i][2..3] = cols 128+n4..128+n4+3.
    unsigned long long x1p[8][4];

    // ======================= Layer 1: virtual [64,512] @ W1 -> [64,256] ===================
    {
        float4 ba = *(const float4*)(b1 + n4);
        float4 bb = *(const float4*)(b1 + 128 + n4);
        unsigned long long p0 = pack2f(ba.x, ba.y);
        unsigned long long p1 = pack2f(ba.z, ba.w);
        unsigned long long p2 = pack2f(bb.x, bb.y);
        unsigned long long p3 = pack2f(bb.z, bb.w);
        #pragma unroll
        for (int i = 0; i < 8; i++) { x1p[i][0]=p0; x1p[i][1]=p1; x1p[i][2]=p2; x1p[i][3]=p3; }
    }

    for (int kc = 0; kc < 32; kc++) {
        cp_wait<0>();              // chunk kc fully resident
        __syncthreads();           // visibility + all warps done with other half
        issue_chunk(kc + 1, Ws, W1, W2, tid);   // chunk 32 == first W2 chunk

        const float* Wb = Ws + (kc & 1) * WS_HALF;
        #pragma unroll
        for (int kk = 0; kk < 4; kk++) {
            const int k = kc * 4 + kk;
            float hi[8], hj[8];
            #pragma unroll
            for (int i = 0; i < 8; i++) {
                hi[i] = Hi[(m0 + i) * HS_LD + k];   // uniform addr -> broadcast
                hj[i] = Hj[(m0 + i) * HS_LD + k];
            }
            #pragma unroll
            for (int blk = 0; blk < 4; blk++) {
                const float* wr = Wb + (blk * 4 + kk) * 256;
                ulonglong2 w0 = *(const ulonglong2*)(wr + n4);        // contiguous 16B/lane
                ulonglong2 w1 = *(const ulonglong2*)(wr + 128 + n4);
                #pragma unroll
                for (int i = 0; i < 8; i++) {
                    float a = (blk == 0) ? hi[i]
                            : (blk == 1) ? hj[i]
                            : (blk == 2) ? fabsf(hi[i] - hj[i])
                                         : hi[i] * hj[i];
                    unsigned long long ap = pack2(a);
                    fma2(x1p[i][0], ap, w0.x);
                    fma2(x1p[i][1], ap, w0.y);
                    fma2(x1p[i][2], ap, w1.x);
                    fma2(x1p[i][3], ap, w1.y);
                }
            }
        }
    }

    // packed ReLU in place
    #pragma unroll
    for (int i = 0; i < 8; i++) {
        #pragma unroll
        for (int q = 0; q < 4; q++) {
            float2 f = unpack2(x1p[i][q]);
            x1p[i][q] = pack2f(fmaxf(f.x, 0.f), fmaxf(f.y, 0.f));
        }
    }

    // ======================= Layer 2: [64,256] @ W2 -> [64,128] =======================
    // A-operand via warp shuffle from packed X1. Chunk 32+c2i covers k in [c2i*32, +32).
    unsigned long long c2[8][2];
    {
        float4 bv = *(const float4*)(b2 + n4);
        unsigned long long p0 = pack2f(bv.x, bv.y);
        unsigned long long p1 = pack2f(bv.z, bv.w);
        #pragma unroll
        for (int i = 0; i < 8; i++) { c2[i][0]=p0; c2[i][1]=p1; }
    }

    #pragma unroll
    for (int half = 0; half < 2; half++) {          // static: selects x1p reg pair
        for (int c4 = 0; c4 < 4; c4++) {            // dynamic
            const int c2i = half * 4 + c4;
            cp_wait<0>();              // chunk 32+c2i resident
            __syncthreads();
            if (c2i < 7) issue_chunk(33 + c2i, Ws, W1, W2, tid);

            const float* Wb = Ws + (c2i & 1) * WS_HALF;
            const int obase = c4 * 8;               // owner-lane base
            for (int kg = 0; kg < 8; kg++) {        // dynamic owner group
                const int owner = obase + kg;
                #pragma unroll
                for (int u = 0; u < 4; u++) {       // static: reg index
                    const int kk = kg * 4 + u;
                    ulonglong2 w = *(const ulonglong2*)(Wb + kk * 128 + n4);
                    #pragma unroll
                    for (int i = 0; i < 8; i++) {
                        float2 f = unpack2(x1p[i][half * 2 + (u >> 1)]);
                        float srcv = (u & 1) ? f.y : f.x;      // static half select
                        float av = __shfl_sync(0xffffffffu, srcv, owner);
                        unsigned long long ap = pack2(av);
                        fma2(c2[i][0], ap, w.x);
                        fma2(c2[i][1], ap, w.y);
                    }
                }
            }
        }
    }

    // ReLU -> X2 smem (reuse Hi region; Hi/Hj dead after layer 1)
    float* X2 = Hi;
    __syncthreads();
    #pragma unroll
    for (int i = 0; i < 8; i++) {
        float2 f0 = unpack2(c2[i][0]);
        float2 f1 = unpack2(c2[i][1]);
        float4 r;
        r.x = fmaxf(f0.x, 0.f); r.y = fmaxf(f0.y, 0.f);
        r.z = fmaxf(f1.x, 0.f); r.w = fmaxf(f1.y, 0.f);
        *(float4*)(X2 + (m0 + i) * HS_LD + n4) = r;
    }
    __syncthreads();

    // ======================= Layer 3: [64,128] @ W3 -> [64,2] =======================
    if (tid < MT * 2) {
        int m = tid >> 1;
        int c = tid & 1;
        const float* x2r = X2 + m * HS_LD;
        const float* w3c = W3s + c * HDIM;
        float4 acc = {0.f, 0.f, 0.f, 0.f};
        #pragma unroll
        for (int k = 0; k < HDIM; k += 4) {
            float4 xv = *(const float4*)(x2r + k);
            float4 wv = *(const float4*)(w3c + k);
            acc.x += xv.x * wv.x; acc.y += xv.y * wv.y;
            acc.z += xv.z * wv.z; acc.w += xv.w * wv.w;
        }
        float sum = b3s[c] + (acc.x + acc.y) + (acc.z + acc.w);
        int e = e0 + m;
        if (e < E) out[e * 2 + c] = sum;
    }
}

extern "C" void kernel_launch(void* const* d_in, const int* in_sizes, int n_in,
                              void* d_out, int out_size) {
    const float* node = (const float*)d_in[0];
    const int*   src  = (const int*)  d_in[1];
    const int*   dst  = (const int*)  d_in[2];
    const float* W1   = (const float*)d_in[3];
    const float* b1   = (const float*)d_in[4];
    const float* W2   = (const float*)d_in[5];
    const float* b2   = (const float*)d_in[6];
    const float* W3   = (const float*)d_in[7];
    const float* b3   = (const float*)d_in[8];
    float* out = (float*)d_out;
    (void)n_in; (void)out_size;

    int E = in_sizes[1];   // src element count = number of edges

    cudaFuncSetAttribute(entity_linker_kernel,
                         cudaFuncAttributeMaxDynamicSharedMemorySize, SMEM_BYTES);

    int grid = (E + MT - 1) / MT;
    entity_linker_kernel<<<grid, THREADS, SMEM_BYTES>>>(
        node, src, dst, W1, b1, W2, b2, W3, b3, out, E);
}

// round 17
// speedup vs baseline: 1.0354x; 1.0354x over previous
#include <cuda_runtime.h>

#define HDIM    128
#define MT      64          // edges per CTA
#define THREADS 256
#define HS_LD   132         // Hi/Hj row stride (floats)
#define X1_LD   260         // X1 overlay row stride (floats), 64*260=16640 <= 16896

// Ws: double buffer, 4096 floats (16KB) per half.
// Layer1 chunk: 4 blk x 4 kk x 256 = 4096. Layer2 chunk: 32 x 128 = 4096.
#define WS_HALF 4096
// SMEM floats: Hi 8448 + Hj 8448 (X1 overlays both) + Ws 8192 + W3s 256 + b3s 8
//            = 25352 floats = 101.4KB -> 2 CTAs/SM (227KB budget)
#define SMEM_FLOATS (8448 + 8448 + 8192 + 256 + 8)
#define SMEM_BYTES  (SMEM_FLOATS * 4)

__device__ __forceinline__ unsigned long long pack2(float x) {
    unsigned long long r;
    asm("mov.b64 %0, {%1, %1};" : "=l"(r) : "f"(x));
    return r;
}
__device__ __forceinline__ unsigned long long pack2f(float lo, float hi) {
    unsigned long long r;
    asm("mov.b64 %0, {%1, %2};" : "=l"(r) : "f"(lo), "f"(hi));
    return r;
}
__device__ __forceinline__ void fma2(unsigned long long& d, unsigned long long a, unsigned long long b) {
    asm("fma.rn.f32x2 %0, %1, %2, %0;" : "+l"(d) : "l"(a), "l"(b));
}
__device__ __forceinline__ float2 unpack2(unsigned long long v) {
    float2 f;
    asm("mov.b64 {%0, %1}, %2;" : "=f"(f.x), "=f"(f.y) : "l"(v));
    return f;
}
__device__ __forceinline__ void cp_async16(float* s, const float* g) {
    unsigned sa = (unsigned)__cvta_generic_to_shared(s);
    asm volatile("cp.async.cg.shared.global [%0], [%1], 16;\n" :: "r"(sa), "l"(g) : "memory");
}
__device__ __forceinline__ void cp_commit() {
    asm volatile("cp.async.commit_group;\n" ::: "memory");
}
template <int N>
__device__ __forceinline__ void cp_wait() {
    asm volatile("cp.async.wait_group %0;\n" :: "n"(N) : "memory");
}

// Issue async copy of weight chunk c into Ws half (c&1). 4096 floats = 1024 f4,
// 4 per thread at 256 threads.
// c in [0,32): W1 chunk (4 blocks x 4 k-rows x 256 cols).
// c in [32,40): W2 chunk (32 k-rows x 128 cols).
__device__ __forceinline__ void issue_chunk(int c, float* Ws,
                                            const float* __restrict__ W1,
                                            const float* __restrict__ W2,
                                            int tid) {
    float* dstb = Ws + (c & 1) * WS_HALF;
    if (c < 32) {
        #pragma unroll
        for (int it = 0; it < 4; it++) {
            int v   = tid + it * THREADS;   // float4 index 0..1023
            int fl  = v * 4;
            int rr  = fl >> 8;              // staged row 0..15
            int col = fl & 255;
            int blk = rr >> 2;
            int kk  = rr & 3;
            const float* g = W1 + (size_t)(blk * HDIM + c * 4 + kk) * 256 + col;
            cp_async16(dstb + rr * 256 + col, g);
        }
    } else {
        int c2 = c - 32;
        #pragma unroll
        for (int it = 0; it < 4; it++) {
            int v   = tid + it * THREADS;
            int fl  = v * 4;
            int rr  = fl >> 7;              // staged row 0..31
            int col = fl & 127;
            const float* g = W2 + (size_t)(c2 * 32 + rr) * 128 + col;
            cp_async16(dstb + rr * 128 + col, g);
        }
    }
    cp_commit();
}

__global__ __launch_bounds__(THREADS, 2)
void entity_linker_kernel(
    const float* __restrict__ node,
    const int*   __restrict__ src,
    const int*   __restrict__ dst,
    const float* __restrict__ W1, const float* __restrict__ b1,
    const float* __restrict__ W2, const float* __restrict__ b2,
    const float* __restrict__ W3, const float* __restrict__ b3,
    float* __restrict__ out, int E)
{
    extern __shared__ float smem[];
    float* Hi  = smem;
    float* Hj  = Hi + MT * HS_LD;
    float* X1v = smem;                  // overlays Hi+Hj after layer 1 (stride X1_LD)
    float* Ws  = Hj + MT * HS_LD;
    float* W3s = Ws + 2 * WS_HALF;      // [2][128] col-major: W3s[c*128+k]
    float* b3s = W3s + 256;

    const int tid = threadIdx.x;
    const int e0  = blockIdx.x * MT;

    // kick off weight chunk 0 ASAP (overlaps the gather)
    issue_chunk(0, Ws, W1, W2, tid);

    // stage W3 (col-major) / b3
    W3s[(tid & 1) * HDIM + (tid >> 1)] = W3[tid];
    if (tid < 2) b3s[tid] = b3[tid];

    // ---- gather Hi / Hj (clamped for tail tile) ----
    #pragma unroll
    for (int it = 0; it < (MT * 32) / THREADS; it++) {
        int v   = tid + it * THREADS;
        int row = v >> 5;
        int seg = v & 31;
        int e = e0 + row; if (e >= E) e = E - 1;
        int s = src[e];
        int d = dst[e];
        float4 a = *(const float4*)(node + (size_t)s * HDIM + seg * 4);
        float4 b = *(const float4*)(node + (size_t)d * HDIM + seg * 4);
        *(float4*)(Hi + row * HS_LD + seg * 4) = a;
        *(float4*)(Hj + row * HS_LD + seg * 4) = b;
    }

    const int tx = tid & 31;          // n-dim: 32 lanes
    const int ty = tid >> 5;          // m-dim: 8 warps, warp owns 8 m-rows
    const int m0 = ty * 8;
    const int n4 = tx * 4;            // lane's base column (4 consecutive floats)

    // ======================= Layer 1: virtual [64,512] @ W1 -> [64,256] ===================
    {
        unsigned long long x1p[8][4];   // accumulators (die after X1 store below)
        {
            float4 ba = *(const float4*)(b1 + n4);
            float4 bb = *(const float4*)(b1 + 128 + n4);
            unsigned long long p0 = pack2f(ba.x, ba.y);
            unsigned long long p1 = pack2f(ba.z, ba.w);
            unsigned long long p2 = pack2f(bb.x, bb.y);
            unsigned long long p3 = pack2f(bb.z, bb.w);
            #pragma unroll
            for (int i = 0; i < 8; i++) { x1p[i][0]=p0; x1p[i][1]=p1; x1p[i][2]=p2; x1p[i][3]=p3; }
        }

        for (int kc = 0; kc < 32; kc++) {
            cp_wait<0>();              // chunk kc fully resident
            __syncthreads();           // visibility + all warps done with other half
            issue_chunk(kc + 1, Ws, W1, W2, tid);   // chunk 32 == first W2 chunk

            const float* Wb = Ws + (kc & 1) * WS_HALF;
            #pragma unroll
            for (int kk = 0; kk < 4; kk++) {
                const int k = kc * 4 + kk;
                float hi[8], hj[8];
                #pragma unroll
                for (int i = 0; i < 8; i++) {
                    hi[i] = Hi[(m0 + i) * HS_LD + k];   // uniform addr -> broadcast
                    hj[i] = Hj[(m0 + i) * HS_LD + k];
                }
                #pragma unroll
                for (int blk = 0; blk < 4; blk++) {
                    const float* wr = Wb + (blk * 4 + kk) * 256;
                    ulonglong2 w0 = *(const ulonglong2*)(wr + n4);        // contiguous 16B/lane
                    ulonglong2 w1 = *(const ulonglong2*)(wr + 128 + n4);
                    #pragma unroll
                    for (int i = 0; i < 8; i++) {
                        float a = (blk == 0) ? hi[i]
                                : (blk == 1) ? hj[i]
                                : (blk == 2) ? fabsf(hi[i] - hj[i])
                                             : hi[i] * hj[i];
                        unsigned long long ap = pack2(a);
                        fma2(x1p[i][0], ap, w0.x);
                        fma2(x1p[i][1], ap, w0.y);
                        fma2(x1p[i][2], ap, w1.x);
                        fma2(x1p[i][3], ap, w1.y);
                    }
                }
            }
        }

        // All warps finished reading Hi/Hj (layer-1 inputs) before overlay writes.
        __syncthreads();

        // ReLU -> X1 overlay (each warp writes only rows m0..m0+7; reads are warp-local)
        #pragma unroll
        for (int i = 0; i < 8; i++) {
            float2 f0 = unpack2(x1p[i][0]);
            float2 f1 = unpack2(x1p[i][1]);
            float2 f2 = unpack2(x1p[i][2]);
            float2 f3 = unpack2(x1p[i][3]);
            float4 ra, rb;
            ra.x = fmaxf(f0.x, 0.f); ra.y = fmaxf(f0.y, 0.f);
            ra.z = fmaxf(f1.x, 0.f); ra.w = fmaxf(f1.y, 0.f);
            rb.x = fmaxf(f2.x, 0.f); rb.y = fmaxf(f2.y, 0.f);
            rb.z = fmaxf(f3.x, 0.f); rb.w = fmaxf(f3.y, 0.f);
            *(float4*)(X1v + (m0 + i) * X1_LD + n4)       = ra;
            *(float4*)(X1v + (m0 + i) * X1_LD + 128 + n4) = rb;
        }
        __syncwarp();   // writer warp == reader warp for these rows
    }

    // ======================= Layer 2: [64,256] @ W2 -> [64,128] =======================
    unsigned long long c2[8][2];
    {
        float4 bv = *(const float4*)(b2 + n4);
        unsigned long long p0 = pack2f(bv.x, bv.y);
        unsigned long long p1 = pack2f(bv.z, bv.w);
        #pragma unroll
        for (int i = 0; i < 8; i++) { c2[i][0]=p0; c2[i][1]=p1; }
    }

    for (int c2i = 0; c2i < 8; c2i++) {
        cp_wait<0>();              // chunk 32+c2i resident
        __syncthreads();
        if (c2i < 7) issue_chunk(33 + c2i, Ws, W1, W2, tid);

        const float* Wb = Ws + (c2i & 1) * WS_HALF;
        #pragma unroll
        for (int kk = 0; kk < 32; kk++) {
            const int k = c2i * 32 + kk;
            ulonglong2 w = *(const ulonglong2*)(Wb + kk * 128 + n4);
            #pragma unroll
            for (int i = 0; i < 8; i++) {
                unsigned long long ap = pack2(X1v[(m0 + i) * X1_LD + k]);  // broadcast
                fma2(c2[i][0], ap, w.x);
                fma2(c2[i][1], ap, w.y);
            }
        }
    }

    // ReLU -> X2 (reuse overlay start; all warps done with X1 reads after this sync)
    float* X2 = smem;
    __syncthreads();
    #pragma unroll
    for (int i = 0; i < 8; i++) {
        float2 f0 = unpack2(c2[i][0]);
        float2 f1 = unpack2(c2[i][1]);
        float4 r;
        r.x = fmaxf(f0.x, 0.f); r.y = fmaxf(f0.y, 0.f);
        r.z = fmaxf(f1.x, 0.f); r.w = fmaxf(f1.y, 0.f);
        *(float4*)(X2 + (m0 + i) * HS_LD + n4) = r;
    }
    __syncthreads();

    // ======================= Layer 3: [64,128] @ W3 -> [64,2] =======================
    if (tid < MT * 2) {
        int m = tid >> 1;
        int c = tid & 1;
        const float* x2r = X2 + m * HS_LD;
        const float* w3c = W3s + c * HDIM;
        float4 acc = {0.f, 0.f, 0.f, 0.f};
        #pragma unroll
        for (int k = 0; k < HDIM; k += 4) {
            float4 xv = *(const float4*)(x2r + k);
            float4 wv = *(const float4*)(w3c + k);
            acc.x += xv.x * wv.x; acc.y += xv.y * wv.y;
            acc.z += xv.z * wv.z; acc.w += xv.w * wv.w;
        }
        float sum = b3s[c] + (acc.x + acc.y) + (acc.z + acc.w);
        int e = e0 + m;
        if (e < E) out[e * 2 + c] = sum;
    }
}

extern "C" void kernel_launch(void* const* d_in, const int* in_sizes, int n_in,
                              void* d_out, int out_size) {
    const float* node = (const float*)d_in[0];
    const int*   src  = (const int*)  d_in[1];
    const int*   dst  = (const int*)  d_in[2];
    const float* W1   = (const float*)d_in[3];
    const float* b1   = (const float*)d_in[4];
    const float* W2   = (const float*)d_in[5];
    const float* b2   = (const float*)d_in[6];
    const float* W3   = (const float*)d_in[7];
    const float* b3   = (const float*)d_in[8];
    float* out = (float*)d_out;
    (void)n_in; (void)out_size;

    int E = in_sizes[1];   // src element count = number of edges

    cudaFuncSetAttribute(entity_linker_kernel,
                         cudaFuncAttributeMaxDynamicSharedMemorySize, SMEM_BYTES);

    int grid = (E + MT - 1) / MT;
    entity_linker_kernel<<<grid, THREADS, SMEM_BYTES>>>(
        node, src, dst, W1, b1, W2, b2, W3, b3, out, E);
}